// round 13
// baseline (speedup 1.0000x reference)
#include <cuda_runtime.h>
#include <cuda_fp16.h>
#include <cstdint>

#define NN 50000
#define NE 640000
#define NF 128
#define EF 128
#define UF 64
#define HID 256
#define NG 64
#define NOUT 128

// ---------------- device global scratch (allocation-free) ----------------
__device__ float g_pre1[(size_t)NN * HID];   // x @ W1[0:128] + b1
__device__ float g_pre3[(size_t)NN * HID];   // x @ W3[0:128]
__device__ float g_aggH[(size_t)NN * HID];   // scatter-sum of h1
__device__ float g_cnt[NN];
__device__ float g_uW3[NG * HID];            // u[g] @ W3[384:448] + b3
__device__ float g_bW[HID];                  // b2 @ W3[128:384]
// fp16 hi-only fragment-layout weight images (m16n8k16); A carries the hi/lo split
__device__ uint32_t g_BfE[8 * 2048];         // W1_bot^T  : 8 chunks x 2048 words
__device__ uint32_t g_BfP[8 * 4096];         // [W1top|W3top]^T : 8 chunks x 4096
__device__ uint32_t g_BfW23[16 * 2048];      // W2@W3mid : 16 chunks x 2048
__device__ uint32_t g_BfW4[16 * 1024];       // W4  : 16 chunks x 1024
__device__ int   g_idx64;

// ---------------- helpers ----------------
__device__ __forceinline__ uint32_t smem_u32(const void* p) {
    uint32_t a;
    asm("{ .reg .u64 t; cvta.to.shared.u64 t, %1; cvt.u32.u64 %0, t; }" : "=r"(a) : "l"(p));
    return a;
}
__device__ __forceinline__ uint32_t pkhf(float lo, float hi) {
    uint32_t r;
    asm("cvt.rn.f16x2.f32 %0, %1, %2;" : "=r"(r) : "f"(hi), "f"(lo));
    return r;
}
__device__ __forceinline__ float hfr(float v) {
    return __half2float(__float2half(v));
}
__device__ __forceinline__ void mma16(float d[4], const uint32_t a[4], uint32_t b0, uint32_t b1) {
    asm volatile("mma.sync.aligned.m16n8k16.row.col.f32.f16.f16.f32 "
                 "{%0,%1,%2,%3}, {%4,%5,%6,%7}, {%8,%9}, {%0,%1,%2,%3};"
                 : "+f"(d[0]), "+f"(d[1]), "+f"(d[2]), "+f"(d[3])
                 : "r"(a[0]), "r"(a[1]), "r"(a[2]), "r"(a[3]), "r"(b0), "r"(b1));
}

#define CP16(dst_u32, src_ptr) \
    asm volatile("cp.async.cg.shared.global [%0], [%1], 16;" :: "r"(dst_u32), "l"(src_ptr) : "memory")
#define CP_COMMIT() asm volatile("cp.async.commit_group;" ::: "memory")
#define CP_WAIT(n)  asm volatile("cp.async.wait_group %0;" :: "n"(n) : "memory")

// ---------------- detect int64/int32 indices ----------------
__global__ void detect_kernel(const unsigned int* __restrict__ ei) {
    if (threadIdx.x == 0 && blockIdx.x == 0) {
        int is64 = 1;
        for (int i = 0; i < 32; ++i)
            if (ei[2 * i + 1] != 0u) { is64 = 0; break; }
        g_idx64 = is64;
    }
}

__global__ void zero_kernel() {
    long long tid = (long long)blockIdx.x * blockDim.x + threadIdx.x;
    long long stride = (long long)gridDim.x * blockDim.x;
    float4* a4 = reinterpret_cast<float4*>(g_aggH);
    const long long n4 = (long long)NN * HID / 4;
    for (long long i = tid; i < n4; i += stride) a4[i] = make_float4(0.f, 0.f, 0.f, 0.f);
    for (long long i = tid; i < NN; i += stride) g_cnt[i] = 0.f;
}

// ---------------- prep: fp16 hi fragment images for edge + pre GEMMs ----------------
__global__ void prep_frag_kernel(const float* __restrict__ W1, const float* __restrict__ W3) {
    int gid = blockIdx.x * blockDim.x + threadIdx.x;   // 0..49151
    if (gid < 16384) {
        int kp = gid >> 8, n = gid & 255;
        int k0 = kp * 2;
        float v0 = W1[(size_t)(128 + k0) * HID + n];
        float v1 = W1[(size_t)(128 + k0 + 1) * HID + n];
        int c = k0 >> 4, kk = k0 & 15, nt = n >> 3;
        int reg = (kk >= 8) ? 1 : 0;
        int lane = (n & 7) * 4 + ((kk & 7) >> 1);
        g_BfE[c * 2048 + (nt * 32 + lane) * 2 + reg] = pkhf(hfr(v0), hfr(v1));
    } else if (gid < 49152) {
        int local = gid - 16384;
        int kp = local >> 9, n = local & 511;
        int k0 = kp * 2;
        const float* Wsrc = (n < 256) ? W1 : W3;
        int nc = n & 255;
        float v0 = Wsrc[(size_t)k0 * HID + nc];
        float v1 = Wsrc[(size_t)(k0 + 1) * HID + nc];
        int c = k0 >> 4, kk = k0 & 15, nt = n >> 3;
        int reg = (kk >= 8) ? 1 : 0;
        int lane = (n & 7) * 4 + ((kk & 7) >> 1);
        g_BfP[c * 4096 + (nt * 32 + lane) * 2 + reg] = pkhf(hfr(v0), hfr(v1));
    }
}

// ---------------- prep: node weight frag images (W23 computed inline) ----------------
__global__ void prep_frag2_kernel(const float* __restrict__ W2, const float* __restrict__ W3,
                                  const float* __restrict__ W4) {
    int gid = blockIdx.x * blockDim.x + threadIdx.x;   // 0..49151
    if (gid < 32768) {
        int kp = gid >> 8, n = gid & 255;
        int k0 = kp * 2;
        float acc0 = 0.f, acc1 = 0.f;
        const float* w2a = W2 + (size_t)k0 * HID;
        const float* w2b = w2a + HID;
        for (int j = 0; j < HID; ++j) {
            float w3 = W3[(size_t)(128 + j) * HID + n];
            acc0 += w2a[j] * w3;
            acc1 += w2b[j] * w3;
        }
        int c = k0 >> 4, kk = k0 & 15, nt = n >> 3;
        int reg = (kk >= 8) ? 1 : 0;
        int lane = (n & 7) * 4 + ((kk & 7) >> 1);
        g_BfW23[c * 2048 + (nt * 32 + lane) * 2 + reg] = pkhf(hfr(acc0), hfr(acc1));
    } else if (gid < 49152) {
        int local = gid - 32768;
        int kp = local >> 7, n = local & 127;
        int k0 = kp * 2;
        float v0 = W4[(size_t)k0 * NOUT + n];
        float v1 = W4[(size_t)(k0 + 1) * NOUT + n];
        int c = k0 >> 4, kk = k0 & 15, nt = n >> 3;
        int reg = (kk >= 8) ? 1 : 0;
        int lane = (n & 7) * 4 + ((kk & 7) >> 1);
        g_BfW4[c * 1024 + (nt * 32 + lane) * 2 + reg] = pkhf(hfr(v0), hfr(v1));
    }
}

// ---------------- prep: uW3 ; bW ----------------
__global__ void prep_u_kernel(const float* __restrict__ u, const float* __restrict__ W3,
                              const float* __restrict__ b3, const float* __restrict__ b2) {
    int g = blockIdx.x, n = threadIdx.x;
    if (g < NG) {
        float acc = b3[n];
        for (int j = 0; j < UF; ++j)
            acc += u[g * UF + j] * W3[(size_t)(384 + j) * HID + n];
        g_uW3[g * HID + n] = acc;
    } else {
        float acc = 0.f;
        for (int j = 0; j < HID; ++j)
            acc += b2[j] * W3[(size_t)(128 + j) * HID + n];
        g_bW[n] = acc;
    }
}

// ---------------- shared MMA building blocks (M=64 tiles: 4 mt per chunk) ----------------
// A frag plane: idx = ((c*4+mt)*32 + (laneT ^ (mt<<2)))*4 + reg
//   laneT=(g&7)*4+t, reg=(g>=8)+2*(kk>=8), g=row&15, mt=row>>4, t=(kk&7)>>1
__device__ __forceinline__ void stage_A(const float* __restrict__ src, int row, int kq, float scale,
                                        uint32_t* __restrict__ sAh, uint32_t* __restrict__ sAl) {
    float4 v[8];
#pragma unroll
    for (int j = 0; j < 8; ++j) v[j] = reinterpret_cast<const float4*>(src)[j];
    const float* vf = reinterpret_cast<const float*>(v);
    const int mt = row >> 4, g = row & 15;
    const int rbase = (g >= 8) ? 1 : 0;
    const int lbase = (g & 7) * 4;
#pragma unroll
    for (int pi = 0; pi < 16; ++pi) {
        float v0 = vf[2 * pi] * scale, v1 = vf[2 * pi + 1] * scale;
        float h0 = hfr(v0), h1 = hfr(v1);
        int k = kq + 2 * pi;
        int c = k >> 4, kk = k & 15;
        int reg = rbase + ((kk >= 8) ? 2 : 0);
        int lane2 = (lbase + ((kk & 7) >> 1)) ^ (mt << 2);
        int idx = ((c * 4 + mt) * 32 + lane2) * 4 + reg;
        sAh[idx] = pkhf(h0, h1);
        sAl[idx] = pkhf(v0 - h0, v1 - h1);
    }
}

// one K=16 chunk, N=256 (8 nt/warp), 2-pass fp16
__device__ __forceinline__ void mma_chunk(const uint32_t* __restrict__ sAh,
                                          const uint32_t* __restrict__ sAl,
                                          const uint32_t* __restrict__ sB,
                                          int c, int warp_m, int warp_n, int lane,
                                          float acc[2][8][4]) {
    uint32_t ah[2][4], al[2][4];
#pragma unroll
    for (int ii = 0; ii < 2; ++ii) {
        int mt = warp_m * 2 + ii;
        int base = ((c * 4 + mt) * 32 + (lane ^ (mt << 2))) * 4;
        *reinterpret_cast<uint4*>(ah[ii]) = *reinterpret_cast<const uint4*>(sAh + base);
        *reinterpret_cast<uint4*>(al[ii]) = *reinterpret_cast<const uint4*>(sAl + base);
    }
#pragma unroll
    for (int ni = 0; ni < 8; ++ni) {
        const int nt = warp_n * 8 + ni;
        uint2 bh = *reinterpret_cast<const uint2*>(sB + (nt * 32 + lane) * 2);
        mma16(acc[0][ni], ah[0], bh.x, bh.y);
        mma16(acc[1][ni], ah[1], bh.x, bh.y);
        mma16(acc[0][ni], al[0], bh.x, bh.y);
        mma16(acc[1][ni], al[1], bh.x, bh.y);
    }
}

// one K=16 chunk, N=128 (4 nt/warp)
__device__ __forceinline__ void mma_chunk4(const uint32_t* __restrict__ sAh,
                                           const uint32_t* __restrict__ sAl,
                                           const uint32_t* __restrict__ sB,
                                           int c, int warp_m, int warp_n, int lane,
                                           float acc[2][4][4]) {
    uint32_t ah[2][4], al[2][4];
#pragma unroll
    for (int ii = 0; ii < 2; ++ii) {
        int mt = warp_m * 2 + ii;
        int base = ((c * 4 + mt) * 32 + (lane ^ (mt << 2))) * 4;
        *reinterpret_cast<uint4*>(ah[ii]) = *reinterpret_cast<const uint4*>(sAh + base);
        *reinterpret_cast<uint4*>(al[ii]) = *reinterpret_cast<const uint4*>(sAl + base);
    }
#pragma unroll
    for (int ni = 0; ni < 4; ++ni) {
        const int nt = warp_n * 4 + ni;
        uint2 bh = *reinterpret_cast<const uint2*>(sB + (nt * 32 + lane) * 2);
        mma16(acc[0][ni], ah[0], bh.x, bh.y);
        mma16(acc[1][ni], ah[1], bh.x, bh.y);
        mma16(acc[0][ni], al[0], bh.x, bh.y);
        mma16(acc[1][ni], al[1], bh.x, bh.y);
    }
}

// ---------------- pre kernel: tile 64 x 256, 256 thr, occ 2 ----------------
__global__ __launch_bounds__(256, 2) void pre_mma_kernel(const float* __restrict__ x,
                                                         const float* __restrict__ b1) {
    extern __shared__ uint32_t smu[];
    uint32_t* sAh = smu;            // 4096 words
    uint32_t* sAl = smu + 4096;     // 4096
    uint32_t* sB  = smu + 8192;     // 16384 (all 8 chunks)

    const int tx = threadIdx.x;
    const int w = tx >> 5, lane = tx & 31;
    const int bm = blockIdx.x * 64;
    const int y = blockIdx.y;
    const uint32_t sBu = smem_u32(sB);

    // load full B (64 KB): 16 CP16/thread
#pragma unroll
    for (int c = 0; c < 8; ++c)
#pragma unroll
        for (int i = 0; i < 2; ++i) {
            int wi = (i * 256 + tx) * 4;
            CP16(sBu + (c * 2048 + wi) * 4, g_BfP + c * 4096 + y * 2048 + wi);
        }
    CP_COMMIT();

    {
        const int row = tx >> 2, kq = (tx & 3) * 32;
        int mg = min(bm + row, NN - 1);
        stage_A(x + (size_t)mg * NF + kq, row, kq, 1.f, sAh, sAl);
    }

    const int warp_m = w >> 2, warp_n = w & 3;
    float acc[2][8][4];
#pragma unroll
    for (int mi = 0; mi < 2; ++mi)
#pragma unroll
        for (int ni = 0; ni < 8; ++ni)
#pragma unroll
            for (int q = 0; q < 4; ++q) acc[mi][ni][q] = 0.f;

    CP_WAIT(0);
    __syncthreads();

#pragma unroll 1
    for (int c = 0; c < 8; ++c)
        mma_chunk(sAh, sAl, sB + c * 2048, c, warp_m, warp_n, lane, acc);

    const int g = lane >> 2, t = lane & 3;
    float* outp = (y == 0) ? g_pre1 : g_pre3;
#pragma unroll
    for (int mi = 0; mi < 2; ++mi) {
        int r0 = bm + warp_m * 32 + mi * 16 + g;
#pragma unroll
        for (int ni = 0; ni < 8; ++ni) {
            int cb = warp_n * 64 + ni * 8 + t * 2;
            float bb0 = 0.f, bb1 = 0.f;
            if (y == 0) { bb0 = b1[cb]; bb1 = b1[cb + 1]; }
            if (r0 < NN)
                *reinterpret_cast<float2*>(outp + (size_t)r0 * HID + cb) =
                    make_float2(acc[mi][ni][0] + bb0, acc[mi][ni][1] + bb1);
            if (r0 + 8 < NN)
                *reinterpret_cast<float2*>(outp + (size_t)(r0 + 8) * HID + cb) =
                    make_float2(acc[mi][ni][2] + bb0, acc[mi][ni][3] + bb1);
        }
    }
}

// ---------------- edge kernel: tile 64 x 256, 256 thr, occ 2 ----------------
#define OLD 260
__global__ __launch_bounds__(256, 2) void edge_mma_kernel(const float* __restrict__ ea,
                                                          const void* __restrict__ eidx) {
    extern __shared__ uint32_t smu[];
    uint32_t* sAh = smu;            // 4096 words
    uint32_t* sAl = smu + 4096;
    uint32_t* sB  = smu + 8192;     // 16384 words
    __shared__ int sRow[64], sCol[64];

    const int tx = threadIdx.x;
    const int w = tx >> 5, lane = tx & 31;
    const int bm = blockIdx.x * 64;
    const int is64 = g_idx64;
    const uint32_t sBu = smem_u32(sB);

#pragma unroll
    for (int c = 0; c < 8; ++c)
#pragma unroll
        for (int i = 0; i < 2; ++i) {
            int wi = (i * 256 + tx) * 4;
            CP16(sBu + (c * 2048 + wi) * 4, g_BfE + c * 2048 + wi);
        }
    CP_COMMIT();

    if (tx < 64) {
        long long e = bm + tx;
        int rr, cc;
        if (is64) {
            rr = (int)reinterpret_cast<const long long*>(eidx)[e];
            cc = (int)reinterpret_cast<const long long*>(eidx)[NE + e];
        } else {
            rr = reinterpret_cast<const int*>(eidx)[e];
            cc = reinterpret_cast<const int*>(eidx)[NE + e];
        }
        sRow[tx] = rr; sCol[tx] = cc;
        atomicAdd(&g_cnt[cc], 1.0f);
    }

    {
        const int row = tx >> 2, kq = (tx & 3) * 32;
        stage_A(ea + (size_t)(bm + row) * EF + kq, row, kq, 1.f, sAh, sAl);
    }

    const int warp_m = w >> 2, warp_n = w & 3;
    float acc[2][8][4];
#pragma unroll
    for (int mi = 0; mi < 2; ++mi)
#pragma unroll
        for (int ni = 0; ni < 8; ++ni)
#pragma unroll
            for (int q = 0; q < 4; ++q) acc[mi][ni][q] = 0.f;

    CP_WAIT(0);
    __syncthreads();

#pragma unroll 1
    for (int c = 0; c < 8; ++c)
        mma_chunk(sAh, sAl, sB + c * 2048, c, warp_m, warp_n, lane, acc);

    // epilogue: stage -> relu(+pre1) -> red.v4 scatter
    __syncthreads();
    float* sOut = reinterpret_cast<float*>(smu);   // 64*260 floats = 66.6 KB
    const int g = lane >> 2, t = lane & 3;
#pragma unroll
    for (int mi = 0; mi < 2; ++mi) {
        int r0 = warp_m * 32 + mi * 16 + g;
#pragma unroll
        for (int ni = 0; ni < 8; ++ni) {
            int cb = warp_n * 64 + ni * 8 + t * 2;
            *reinterpret_cast<float2*>(sOut + r0 * OLD + cb) =
                make_float2(acc[mi][ni][0], acc[mi][ni][1]);
            *reinterpret_cast<float2*>(sOut + (r0 + 8) * OLD + cb) =
                make_float2(acc[mi][ni][2], acc[mi][ni][3]);
        }
    }
    __syncthreads();

#pragma unroll
    for (int rr = 0; rr < 8; ++rr) {
        const int row = w * 8 + rr;
        const int j0 = lane * 8;
        const float* prow = g_pre1 + (size_t)sRow[row] * HID + j0;
        float* arow = g_aggH + (size_t)sCol[row] * HID + j0;
        float4 v0 = *reinterpret_cast<const float4*>(sOut + row * OLD + j0);
        float4 v1 = *reinterpret_cast<const float4*>(sOut + row * OLD + j0 + 4);
        float4 p0 = *reinterpret_cast<const float4*>(prow);
        float4 p1 = *reinterpret_cast<const float4*>(prow + 4);
        float a0 = fmaxf(v0.x + p0.x, 0.f), a1 = fmaxf(v0.y + p0.y, 0.f);
        float a2 = fmaxf(v0.z + p0.z, 0.f), a3 = fmaxf(v0.w + p0.w, 0.f);
        float a4 = fmaxf(v1.x + p1.x, 0.f), a5 = fmaxf(v1.y + p1.y, 0.f);
        float a6 = fmaxf(v1.z + p1.z, 0.f), a7 = fmaxf(v1.w + p1.w, 0.f);
        asm volatile("red.global.add.v4.f32 [%0], {%1,%2,%3,%4};"
            :: "l"(arow), "f"(a0), "f"(a1), "f"(a2), "f"(a3) : "memory");
        asm volatile("red.global.add.v4.f32 [%0], {%1,%2,%3,%4};"
            :: "l"(arow + 4), "f"(a4), "f"(a5), "f"(a6), "f"(a7) : "memory");
    }
}

// ---------------- node kernel: tile 64 nodes, K=256, 256 thr, occ 2 ----------------
__global__ __launch_bounds__(256, 2) void node_mma_kernel(const void* __restrict__ batch,
                                                          const float* __restrict__ b4,
                                                          float* __restrict__ out) {
    extern __shared__ uint32_t smu[];
    uint32_t* sAh = smu;            // 8192 words (16 chunks x 4 mt)
    uint32_t* sAl = smu + 8192;     // 8192
    uint32_t* sB  = smu + 16384;    // 2 x 2048
    __shared__ int sBat[64];
    __shared__ float sFlag[64];

    const int tx = threadIdx.x;
    const int w = tx >> 5, lane = tx & 31;
    const int bm = blockIdx.x * 64;
    const int is64 = g_idx64;
    const uint32_t sBu = smem_u32(sB);

#pragma unroll
    for (int i = 0; i < 2; ++i) {
        int wi = (i * 256 + tx) * 4;
        CP16(sBu + wi * 4, g_BfW23 + wi);
    }
    CP_COMMIT();

    if (tx < 64) {
        int mg = min(bm + tx, NN - 1);
        float cnt = g_cnt[mg];
        sFlag[tx] = (cnt > 0.f) ? 1.f : 0.f;
        sBat[tx] = is64 ? (int)reinterpret_cast<const long long*>(batch)[mg]
                        : reinterpret_cast<const int*>(batch)[mg];
    }

    {
        const int row = tx >> 2;
        int mg = min(bm + row, NN - 1);
        float inv = 1.f / fmaxf(g_cnt[mg], 1.f);
        const float* src = g_aggH + (size_t)mg * HID;
        int kq0 = (tx & 3) * 32;
        stage_A(src + kq0, row, kq0, inv, sAh, sAl);
        stage_A(src + kq0 + 128, row, kq0 + 128, inv, sAh, sAl);
    }

    const int warp_m = w >> 2, warp_n = w & 3;
    float acc[2][8][4];
#pragma unroll
    for (int mi = 0; mi < 2; ++mi)
#pragma unroll
        for (int ni = 0; ni < 8; ++ni)
#pragma unroll
            for (int q = 0; q < 4; ++q) acc[mi][ni][q] = 0.f;

#pragma unroll 1
    for (int c = 0; c < 16; ++c) {
        const int buf = c & 1;
        CP_WAIT(0);
        __syncthreads();
        if (c < 15) {
#pragma unroll
            for (int i = 0; i < 2; ++i) {
                int wi = (i * 256 + tx) * 4;
                CP16(sBu + ((buf ^ 1) * 2048 + wi) * 4, g_BfW23 + (c + 1) * 2048 + wi);
            }
            CP_COMMIT();
        }
        mma_chunk(sAh, sAl, sB + buf * 2048, c, warp_m, warp_n, lane, acc);
    }
    __syncthreads();

    // first W4 chunk into buf 0
    CP16(sBu + (tx * 4) * 4, g_BfW4 + tx * 4);
    CP_COMMIT();

    // L3 epilogue: hid = relu(acc + pre3 + uW3 + bW*flag), pack into A frags
    const int g = lane >> 2, t = lane & 3;
#pragma unroll
    for (int mi = 0; mi < 2; ++mi) {
        const int mt = warp_m * 2 + mi;
        const int rA = warp_m * 32 + mi * 16 + g;
        const int mgA = min(bm + rA, NN - 1);
        const int mgB = min(bm + rA + 8, NN - 1);
        const float flA = sFlag[rA], flB = sFlag[rA + 8];
        const float* p3A = g_pre3 + (size_t)mgA * HID;
        const float* p3B = g_pre3 + (size_t)mgB * HID;
        const float* uwA = g_uW3 + (size_t)sBat[rA] * HID;
        const float* uwB = g_uW3 + (size_t)sBat[rA + 8] * HID;
#pragma unroll
        for (int ni = 0; ni < 8; ++ni) {
            int cb = warp_n * 64 + ni * 8 + t * 2;
            int c = cb >> 4, kk = cb & 15;
            int lane2 = ((g & 7) * 4 + ((kk & 7) >> 1)) ^ (mt << 2);
            int idx = ((c * 4 + mt) * 32 + lane2) * 4 + ((kk >= 8) ? 2 : 0);
            float2 bw = *reinterpret_cast<const float2*>(g_bW + cb);
            {
                float2 p3 = *reinterpret_cast<const float2*>(p3A + cb);
                float2 uw = *reinterpret_cast<const float2*>(uwA + cb);
                float h0 = fmaxf(acc[mi][ni][0] + p3.x + uw.x + bw.x * flA, 0.f);
                float h1 = fmaxf(acc[mi][ni][1] + p3.y + uw.y + bw.y * flA, 0.f);
                float b0 = hfr(h0), b1v = hfr(h1);
                sAh[idx] = pkhf(b0, b1v);
                sAl[idx] = pkhf(h0 - b0, h1 - b1v);
            }
            {
                float2 p3 = *reinterpret_cast<const float2*>(p3B + cb);
                float2 uw = *reinterpret_cast<const float2*>(uwB + cb);
                float h0 = fmaxf(acc[mi][ni][2] + p3.x + uw.x + bw.x * flB, 0.f);
                float h1 = fmaxf(acc[mi][ni][3] + p3.y + uw.y + bw.y * flB, 0.f);
                float b0 = hfr(h0), b1v = hfr(h1);
                sAh[idx + 1] = pkhf(b0, b1v);
                sAl[idx + 1] = pkhf(h0 - b0, h1 - b1v);
            }
        }
    }
    __syncthreads();

    // L4: hid @ W4 (K=256, N=128)
    float acc2[2][4][4];
#pragma unroll
    for (int mi = 0; mi < 2; ++mi)
#pragma unroll
        for (int ni = 0; ni < 4; ++ni)
#pragma unroll
            for (int q = 0; q < 4; ++q) acc2[mi][ni][q] = 0.f;

#pragma unroll 1
    for (int c = 0; c < 16; ++c) {
        const int buf = c & 1;
        CP_WAIT(0);
        __syncthreads();
        if (c < 15) {
            CP16(sBu + ((buf ^ 1) * 2048 + tx * 4) * 4, g_BfW4 + (c + 1) * 1024 + tx * 4);
            CP_COMMIT();
        }
        mma_chunk4(sAh, sAl, sB + buf * 2048, c, warp_m, warp_n, lane, acc2);
    }

#pragma unroll
    for (int mi = 0; mi < 2; ++mi) {
        int r0 = bm + warp_m * 32 + mi * 16 + g;
#pragma unroll
        for (int ni = 0; ni < 4; ++ni) {
            int cb = warp_n * 32 + ni * 8 + t * 2;
            float2 bb = *reinterpret_cast<const float2*>(b4 + cb);
            if (r0 < NN)
                *reinterpret_cast<float2*>(out + (size_t)r0 * NOUT + cb) =
                    make_float2(acc2[mi][ni][0] + bb.x, acc2[mi][ni][1] + bb.y);
            if (r0 + 8 < NN)
                *reinterpret_cast<float2*>(out + (size_t)(r0 + 8) * NOUT + cb) =
                    make_float2(acc2[mi][ni][2] + bb.x, acc2[mi][ni][3] + bb.y);
        }
    }
}

// ---------------------------------------------------------------------------
extern "C" void kernel_launch(void* const* d_in, const int* in_sizes, int n_in,
                              void* d_out, int out_size) {
    const float* x  = (const float*)d_in[0];
    const void*  ei = d_in[1];
    const float* ea = (const float*)d_in[2];
    const float* u  = (const float*)d_in[3];
    const void*  bt = d_in[4];
    const float* W1 = (const float*)d_in[5];
    const float* b1 = (const float*)d_in[6];
    const float* W2 = (const float*)d_in[7];
    const float* b2 = (const float*)d_in[8];
    const float* W3 = (const float*)d_in[9];
    const float* b3 = (const float*)d_in[10];
    const float* W4 = (const float*)d_in[11];
    const float* b4 = (const float*)d_in[12];
    float* out = (float*)d_out;

    const int smem_pre  = 24576 * 4;            // 96 KB -> occ 2
    const int smem_edge = 24576 * 4;            // 96 KB (sOut 66.6 KB reuses) -> occ 2
    const int smem_node = 20480 * 4;            // 80 KB -> occ 2

    cudaFuncSetAttribute(pre_mma_kernel, cudaFuncAttributeMaxDynamicSharedMemorySize, smem_pre);
    cudaFuncSetAttribute(edge_mma_kernel, cudaFuncAttributeMaxDynamicSharedMemorySize, smem_edge);
    cudaFuncSetAttribute(node_mma_kernel, cudaFuncAttributeMaxDynamicSharedMemorySize, smem_node);

    detect_kernel<<<1, 32>>>((const unsigned int*)ei);
    zero_kernel<<<1024, 256>>>();
    prep_frag_kernel<<<192, 256>>>(W1, W3);
    prep_frag2_kernel<<<192, 256>>>(W2, W3, W4);
    prep_u_kernel<<<NG + 1, 256>>>(u, W3, b3, b2);
    pre_mma_kernel<<<dim3((NN + 63) / 64, 2), 256, smem_pre>>>(x, b1);
    edge_mma_kernel<<<NE / 64, 256, smem_edge>>>(ea, ei);
    node_mma_kernel<<<(NN + 63) / 64, 256, smem_node>>>(bt, b4, out);
}

// round 14
// speedup vs baseline: 1.4260x; 1.4260x over previous
#include <cuda_runtime.h>
#include <cuda_fp16.h>
#include <cstdint>

#define NN 50000
#define NE 640000
#define NF 128
#define EF 128
#define UF 64
#define HID 256
#define NG 64
#define NOUT 128

// ---------------- device global scratch (allocation-free) ----------------
__device__ float g_pre1[(size_t)NN * HID];   // x @ W1[0:128] + b1
__device__ float g_pre3[(size_t)NN * HID];   // x @ W3[0:128]
__device__ float g_aggH[(size_t)NN * HID];   // scatter-sum of h1
__device__ float g_cnt[NN];
__device__ float g_uW3[NG * HID];            // u[g] @ W3[384:448] + b3
__device__ float g_bW[HID];                  // b2 @ W3[128:384]
// fp16 hi-only fragment-layout weight images (m16n8k16)
__device__ uint32_t g_BfE[8 * 2048];         // W1_bot^T  : 8 chunks x 2048 words
__device__ uint32_t g_BfP[8 * 4096];         // [W1top|W3top]^T : 8 chunks x 4096
__device__ uint32_t g_BfW23[16 * 2048];      // W2@W3mid : 16 chunks x 2048
__device__ uint32_t g_BfW4[16 * 1024];       // W4  : 16 chunks x 1024
__device__ int   g_idx64;

// ---------------- helpers ----------------
__device__ __forceinline__ uint32_t smem_u32(const void* p) {
    uint32_t a;
    asm("{ .reg .u64 t; cvta.to.shared.u64 t, %1; cvt.u32.u64 %0, t; }" : "=r"(a) : "l"(p));
    return a;
}
__device__ __forceinline__ uint32_t pkhf(float lo, float hi) {
    uint32_t r;
    asm("cvt.rn.f16x2.f32 %0, %1, %2;" : "=r"(r) : "f"(hi), "f"(lo));
    return r;
}
__device__ __forceinline__ float hfr(float v) {
    return __half2float(__float2half(v));
}
__device__ __forceinline__ void mma16(float d[4], const uint32_t a[4], uint32_t b0, uint32_t b1) {
    asm volatile("mma.sync.aligned.m16n8k16.row.col.f32.f16.f16.f32 "
                 "{%0,%1,%2,%3}, {%4,%5,%6,%7}, {%8,%9}, {%0,%1,%2,%3};"
                 : "+f"(d[0]), "+f"(d[1]), "+f"(d[2]), "+f"(d[3])
                 : "r"(a[0]), "r"(a[1]), "r"(a[2]), "r"(a[3]), "r"(b0), "r"(b1));
}

#define CP16(dst_u32, src_ptr) \
    asm volatile("cp.async.cg.shared.global [%0], [%1], 16;" :: "r"(dst_u32), "l"(src_ptr) : "memory")
#define CP_COMMIT() asm volatile("cp.async.commit_group;" ::: "memory")
#define CP_WAIT(n)  asm volatile("cp.async.wait_group %0;" :: "n"(n) : "memory")

// ---------------- detect int64/int32 indices ----------------
__global__ void detect_kernel(const unsigned int* __restrict__ ei) {
    if (threadIdx.x == 0 && blockIdx.x == 0) {
        int is64 = 1;
        for (int i = 0; i < 32; ++i)
            if (ei[2 * i + 1] != 0u) { is64 = 0; break; }
        g_idx64 = is64;
    }
}

__global__ void zero_kernel() {
    long long tid = (long long)blockIdx.x * blockDim.x + threadIdx.x;
    long long stride = (long long)gridDim.x * blockDim.x;
    float4* a4 = reinterpret_cast<float4*>(g_aggH);
    const long long n4 = (long long)NN * HID / 4;
    for (long long i = tid; i < n4; i += stride) a4[i] = make_float4(0.f, 0.f, 0.f, 0.f);
    for (long long i = tid; i < NN; i += stride) g_cnt[i] = 0.f;
}

// ---------------- prep: fp16 hi fragment images for edge + pre GEMMs ----------------
__global__ void prep_frag_kernel(const float* __restrict__ W1, const float* __restrict__ W3) {
    int gid = blockIdx.x * blockDim.x + threadIdx.x;   // 0..49151
    if (gid < 16384) {
        int kp = gid >> 8, n = gid & 255;
        int k0 = kp * 2;
        float v0 = W1[(size_t)(128 + k0) * HID + n];
        float v1 = W1[(size_t)(128 + k0 + 1) * HID + n];
        int c = k0 >> 4, kk = k0 & 15, nt = n >> 3;
        int reg = (kk >= 8) ? 1 : 0;
        int lane = (n & 7) * 4 + ((kk & 7) >> 1);
        g_BfE[c * 2048 + (nt * 32 + lane) * 2 + reg] = pkhf(hfr(v0), hfr(v1));
    } else if (gid < 49152) {
        int local = gid - 16384;
        int kp = local >> 9, n = local & 511;
        int k0 = kp * 2;
        const float* Wsrc = (n < 256) ? W1 : W3;
        int nc = n & 255;
        float v0 = Wsrc[(size_t)k0 * HID + nc];
        float v1 = Wsrc[(size_t)(k0 + 1) * HID + nc];
        int c = k0 >> 4, kk = k0 & 15, nt = n >> 3;
        int reg = (kk >= 8) ? 1 : 0;
        int lane = (n & 7) * 4 + ((kk & 7) >> 1);
        g_BfP[c * 4096 + (nt * 32 + lane) * 2 + reg] = pkhf(hfr(v0), hfr(v1));
    }
}

// ---------------- prep: node weight frag images (W23 computed inline) ----------------
__global__ void prep_frag2_kernel(const float* __restrict__ W2, const float* __restrict__ W3,
                                  const float* __restrict__ W4) {
    int gid = blockIdx.x * blockDim.x + threadIdx.x;   // 0..49151
    if (gid < 32768) {
        int kp = gid >> 8, n = gid & 255;
        int k0 = kp * 2;
        float acc0 = 0.f, acc1 = 0.f;
        const float* w2a = W2 + (size_t)k0 * HID;
        const float* w2b = w2a + HID;
        for (int j = 0; j < HID; ++j) {
            float w3 = W3[(size_t)(128 + j) * HID + n];
            acc0 += w2a[j] * w3;
            acc1 += w2b[j] * w3;
        }
        int c = k0 >> 4, kk = k0 & 15, nt = n >> 3;
        int reg = (kk >= 8) ? 1 : 0;
        int lane = (n & 7) * 4 + ((kk & 7) >> 1);
        g_BfW23[c * 2048 + (nt * 32 + lane) * 2 + reg] = pkhf(hfr(acc0), hfr(acc1));
    } else if (gid < 49152) {
        int local = gid - 32768;
        int kp = local >> 7, n = local & 127;
        int k0 = kp * 2;
        float v0 = W4[(size_t)k0 * NOUT + n];
        float v1 = W4[(size_t)(k0 + 1) * NOUT + n];
        int c = k0 >> 4, kk = k0 & 15, nt = n >> 3;
        int reg = (kk >= 8) ? 1 : 0;
        int lane = (n & 7) * 4 + ((kk & 7) >> 1);
        g_BfW4[c * 1024 + (nt * 32 + lane) * 2 + reg] = pkhf(hfr(v0), hfr(v1));
    }
}

// ---------------- prep: uW3 ; bW ----------------
__global__ void prep_u_kernel(const float* __restrict__ u, const float* __restrict__ W3,
                              const float* __restrict__ b3, const float* __restrict__ b2) {
    int g = blockIdx.x, n = threadIdx.x;
    if (g < NG) {
        float acc = b3[n];
        for (int j = 0; j < UF; ++j)
            acc += u[g * UF + j] * W3[(size_t)(384 + j) * HID + n];
        g_uW3[g * HID + n] = acc;
    } else {
        float acc = 0.f;
        for (int j = 0; j < HID; ++j)
            acc += b2[j] * W3[(size_t)(128 + j) * HID + n];
        g_bW[n] = acc;
    }
}

// ---------------- shared MMA building blocks (M=128 tiles: 8 mt per chunk) ----------------
// A frag plane: idx = ((c*8+mt)*32 + (laneT ^ (mt<<2)))*4 + reg
__device__ __forceinline__ void stage_A(const float* __restrict__ src, int row, int kq, float scale,
                                        uint32_t* __restrict__ sAh, uint32_t* __restrict__ sAl) {
    float4 v[8];
#pragma unroll
    for (int j = 0; j < 8; ++j) v[j] = reinterpret_cast<const float4*>(src)[j];
    const float* vf = reinterpret_cast<const float*>(v);
    const int mt = row >> 4, g = row & 15;
    const int rbase = (g >= 8) ? 1 : 0;
    const int lbase = (g & 7) * 4;
#pragma unroll
    for (int pi = 0; pi < 16; ++pi) {
        float v0 = vf[2 * pi] * scale, v1 = vf[2 * pi + 1] * scale;
        float h0 = hfr(v0), h1 = hfr(v1);
        int k = kq + 2 * pi;
        int c = k >> 4, kk = k & 15;
        int reg = rbase + ((kk >= 8) ? 2 : 0);
        int lane2 = (lbase + ((kk & 7) >> 1)) ^ (mt << 2);
        int idx = ((c * 8 + mt) * 32 + lane2) * 4 + reg;
        sAh[idx] = pkhf(h0, h1);
        sAl[idx] = pkhf(v0 - h0, v1 - h1);
    }
}

// hi-only variant (single-pass consumers)
__device__ __forceinline__ void stage_A_hi(const float* __restrict__ src, int row, int kq, float scale,
                                           uint32_t* __restrict__ sAh) {
    float4 v[8];
#pragma unroll
    for (int j = 0; j < 8; ++j) v[j] = reinterpret_cast<const float4*>(src)[j];
    const float* vf = reinterpret_cast<const float*>(v);
    const int mt = row >> 4, g = row & 15;
    const int rbase = (g >= 8) ? 1 : 0;
    const int lbase = (g & 7) * 4;
#pragma unroll
    for (int pi = 0; pi < 16; ++pi) {
        float v0 = vf[2 * pi] * scale, v1 = vf[2 * pi + 1] * scale;
        int k = kq + 2 * pi;
        int c = k >> 4, kk = k & 15;
        int reg = rbase + ((kk >= 8) ? 2 : 0);
        int lane2 = (lbase + ((kk & 7) >> 1)) ^ (mt << 2);
        int idx = ((c * 8 + mt) * 32 + lane2) * 4 + reg;
        sAh[idx] = pkhf(hfr(v0), hfr(v1));
    }
}

// 2-pass chunk, N=256 (pre kernel)
__device__ __forceinline__ void mma_chunk(const uint32_t* __restrict__ sAh,
                                          const uint32_t* __restrict__ sAl,
                                          const uint32_t* __restrict__ sB,
                                          int c, int warp_m, int warp_n, int lane,
                                          float acc[2][8][4]) {
    uint32_t ah[2][4], al[2][4];
#pragma unroll
    for (int ii = 0; ii < 2; ++ii) {
        int mt = warp_m * 2 + ii;
        int base = ((c * 8 + mt) * 32 + (lane ^ (mt << 2))) * 4;
        *reinterpret_cast<uint4*>(ah[ii]) = *reinterpret_cast<const uint4*>(sAh + base);
        *reinterpret_cast<uint4*>(al[ii]) = *reinterpret_cast<const uint4*>(sAl + base);
    }
#pragma unroll
    for (int ni = 0; ni < 8; ++ni) {
        const int nt = warp_n * 8 + ni;
        uint2 bh = *reinterpret_cast<const uint2*>(sB + (nt * 32 + lane) * 2);
        mma16(acc[0][ni], ah[0], bh.x, bh.y);
        mma16(acc[1][ni], ah[1], bh.x, bh.y);
        mma16(acc[0][ni], al[0], bh.x, bh.y);
        mma16(acc[1][ni], al[1], bh.x, bh.y);
    }
}

// single-pass chunk, N=256 (edge + node L3)
__device__ __forceinline__ void mma_chunk1(const uint32_t* __restrict__ sAh,
                                           const uint32_t* __restrict__ sB,
                                           int c, int warp_m, int warp_n, int lane,
                                           float acc[2][8][4]) {
    uint32_t ah[2][4];
#pragma unroll
    for (int ii = 0; ii < 2; ++ii) {
        int mt = warp_m * 2 + ii;
        int base = ((c * 8 + mt) * 32 + (lane ^ (mt << 2))) * 4;
        *reinterpret_cast<uint4*>(ah[ii]) = *reinterpret_cast<const uint4*>(sAh + base);
    }
#pragma unroll
    for (int ni = 0; ni < 8; ++ni) {
        const int nt = warp_n * 8 + ni;
        uint2 bh = *reinterpret_cast<const uint2*>(sB + (nt * 32 + lane) * 2);
        mma16(acc[0][ni], ah[0], bh.x, bh.y);
        mma16(acc[1][ni], ah[1], bh.x, bh.y);
    }
}

// single-pass chunk, N=128 (node L4)
__device__ __forceinline__ void mma_chunk41(const uint32_t* __restrict__ sAh,
                                            const uint32_t* __restrict__ sB,
                                            int c, int warp_m, int warp_n, int lane,
                                            float acc[2][4][4]) {
    uint32_t ah[2][4];
#pragma unroll
    for (int ii = 0; ii < 2; ++ii) {
        int mt = warp_m * 2 + ii;
        int base = ((c * 8 + mt) * 32 + (lane ^ (mt << 2))) * 4;
        *reinterpret_cast<uint4*>(ah[ii]) = *reinterpret_cast<const uint4*>(sAh + base);
    }
#pragma unroll
    for (int ni = 0; ni < 4; ++ni) {
        const int nt = warp_n * 4 + ni;
        uint2 bh = *reinterpret_cast<const uint2*>(sB + (nt * 32 + lane) * 2);
        mma16(acc[0][ni], ah[0], bh.x, bh.y);
        mma16(acc[1][ni], ah[1], bh.x, bh.y);
    }
}

// ---------------- pre kernel (2-pass, full-resident B): tile 128 x 256 ----------------
__global__ __launch_bounds__(512, 1) void pre_mma_kernel(const float* __restrict__ x,
                                                         const float* __restrict__ b1) {
    extern __shared__ uint32_t smu[];
    uint32_t* sAh = smu;            // 8192 words
    uint32_t* sAl = smu + 8192;     // 8192
    uint32_t* sB  = smu + 16384;    // 16384 (all 8 chunks)

    const int tx = threadIdx.x;
    const int w = tx >> 5, lane = tx & 31;
    const int bm = blockIdx.x * 128;
    const int y = blockIdx.y;
    const uint32_t sBu = smem_u32(sB);

#pragma unroll
    for (int c = 0; c < 8; ++c)
        CP16(sBu + (c * 2048 + tx * 4) * 4, g_BfP + c * 4096 + y * 2048 + tx * 4);
    CP_COMMIT();

    {
        const int row = tx >> 2, kq = (tx & 3) * 32;
        int mg = min(bm + row, NN - 1);
        stage_A(x + (size_t)mg * NF + kq, row, kq, 1.f, sAh, sAl);
    }

    const int warp_m = w >> 2, warp_n = w & 3;
    float acc[2][8][4];
#pragma unroll
    for (int mi = 0; mi < 2; ++mi)
#pragma unroll
        for (int ni = 0; ni < 8; ++ni)
#pragma unroll
            for (int q = 0; q < 4; ++q) acc[mi][ni][q] = 0.f;

    CP_WAIT(0);
    __syncthreads();

#pragma unroll 1
    for (int c = 0; c < 8; ++c)
        mma_chunk(sAh, sAl, sB + c * 2048, c, warp_m, warp_n, lane, acc);

    const int g = lane >> 2, t = lane & 3;
    float* outp = (y == 0) ? g_pre1 : g_pre3;
#pragma unroll
    for (int mi = 0; mi < 2; ++mi) {
        int r0 = bm + warp_m * 32 + mi * 16 + g;
#pragma unroll
        for (int ni = 0; ni < 8; ++ni) {
            int cb = warp_n * 64 + ni * 8 + t * 2;
            float bb0 = 0.f, bb1 = 0.f;
            if (y == 0) { bb0 = b1[cb]; bb1 = b1[cb + 1]; }
            if (r0 < NN)
                *reinterpret_cast<float2*>(outp + (size_t)r0 * HID + cb) =
                    make_float2(acc[mi][ni][0] + bb0, acc[mi][ni][1] + bb1);
            if (r0 + 8 < NN)
                *reinterpret_cast<float2*>(outp + (size_t)(r0 + 8) * HID + cb) =
                    make_float2(acc[mi][ni][2] + bb0, acc[mi][ni][3] + bb1);
        }
    }
}

// ---------------- edge kernel (single-pass fp16, full-resident B): 128 edges x 256 ----------------
#define OLD 260
__global__ __launch_bounds__(512, 1) void edge_mma_kernel(const float* __restrict__ ea,
                                                          const void* __restrict__ eidx) {
    extern __shared__ uint32_t smu[];
    uint32_t* sAh = smu;            // 8192 words (hi only)
    uint32_t* sB  = smu + 8192;     // 16384 words (all 8 chunks)
    __shared__ int sRow[128], sCol[128];

    const int tx = threadIdx.x;
    const int w = tx >> 5, lane = tx & 31;
    const int bm = blockIdx.x * 128;
    const int is64 = g_idx64;
    const uint32_t sBu = smem_u32(sB);

#pragma unroll
    for (int c = 0; c < 8; ++c)
        CP16(sBu + (c * 2048 + tx * 4) * 4, g_BfE + c * 2048 + tx * 4);
    CP_COMMIT();

    if (tx < 128) {
        long long e = bm + tx;
        int rr, cc;
        if (is64) {
            rr = (int)reinterpret_cast<const long long*>(eidx)[e];
            cc = (int)reinterpret_cast<const long long*>(eidx)[NE + e];
        } else {
            rr = reinterpret_cast<const int*>(eidx)[e];
            cc = reinterpret_cast<const int*>(eidx)[NE + e];
        }
        sRow[tx] = rr; sCol[tx] = cc;
        atomicAdd(&g_cnt[cc], 1.0f);
    }

    {
        const int row = tx >> 2, kq = (tx & 3) * 32;
        stage_A_hi(ea + (size_t)(bm + row) * EF + kq, row, kq, 1.f, sAh);
    }

    const int warp_m = w >> 2, warp_n = w & 3;
    float acc[2][8][4];
#pragma unroll
    for (int mi = 0; mi < 2; ++mi)
#pragma unroll
        for (int ni = 0; ni < 8; ++ni)
#pragma unroll
            for (int q = 0; q < 4; ++q) acc[mi][ni][q] = 0.f;

    CP_WAIT(0);
    __syncthreads();

#pragma unroll 1
    for (int c = 0; c < 8; ++c)
        mma_chunk1(sAh, sB + c * 2048, c, warp_m, warp_n, lane, acc);

    // epilogue: single full-width pass: stage -> relu(+pre1) -> red.v4 scatter
    __syncthreads();
    float* sOut = reinterpret_cast<float*>(smu);   // 128*260 floats = 133.1 KB
    const int g = lane >> 2, t = lane & 3;
#pragma unroll
    for (int mi = 0; mi < 2; ++mi) {
        int r0 = warp_m * 32 + mi * 16 + g;
#pragma unroll
        for (int ni = 0; ni < 8; ++ni) {
            int cb = warp_n * 64 + ni * 8 + t * 2;
            *reinterpret_cast<float2*>(sOut + r0 * OLD + cb) =
                make_float2(acc[mi][ni][0], acc[mi][ni][1]);
            *reinterpret_cast<float2*>(sOut + (r0 + 8) * OLD + cb) =
                make_float2(acc[mi][ni][2], acc[mi][ni][3]);
        }
    }
    __syncthreads();

#pragma unroll
    for (int rr = 0; rr < 8; ++rr) {
        const int row = w * 8 + rr;
        const int j0 = lane * 8;
        const float* prow = g_pre1 + (size_t)sRow[row] * HID + j0;
        float* arow = g_aggH + (size_t)sCol[row] * HID + j0;
        float4 v0 = *reinterpret_cast<const float4*>(sOut + row * OLD + j0);
        float4 v1 = *reinterpret_cast<const float4*>(sOut + row * OLD + j0 + 4);
        float4 p0 = *reinterpret_cast<const float4*>(prow);
        float4 p1 = *reinterpret_cast<const float4*>(prow + 4);
        float a0 = fmaxf(v0.x + p0.x, 0.f), a1 = fmaxf(v0.y + p0.y, 0.f);
        float a2 = fmaxf(v0.z + p0.z, 0.f), a3 = fmaxf(v0.w + p0.w, 0.f);
        float a4 = fmaxf(v1.x + p1.x, 0.f), a5 = fmaxf(v1.y + p1.y, 0.f);
        float a6 = fmaxf(v1.z + p1.z, 0.f), a7 = fmaxf(v1.w + p1.w, 0.f);
        asm volatile("red.global.add.v4.f32 [%0], {%1,%2,%3,%4};"
            :: "l"(arow), "f"(a0), "f"(a1), "f"(a2), "f"(a3) : "memory");
        asm volatile("red.global.add.v4.f32 [%0], {%1,%2,%3,%4};"
            :: "l"(arow + 4), "f"(a4), "f"(a5), "f"(a6), "f"(a7) : "memory");
    }
}

// ---------------- node kernel (single-pass fp16): 128 nodes, K=256 L3, then L4 ----------------
__global__ __launch_bounds__(512, 1) void node_mma_kernel(const void* __restrict__ batch,
                                                          const float* __restrict__ b4,
                                                          float* __restrict__ out) {
    extern __shared__ uint32_t smu[];
    uint32_t* sAh = smu;            // 16384 words (16 chunks, hi only)
    uint32_t* sB  = smu + 16384;    // 2 x 2048
    __shared__ int sBat[128];
    __shared__ float sFlag[128];

    const int tx = threadIdx.x;
    const int w = tx >> 5, lane = tx & 31;
    const int bm = blockIdx.x * 128;
    const int is64 = g_idx64;
    const uint32_t sBu = smem_u32(sB);

    CP16(sBu + (tx * 4) * 4, g_BfW23 + tx * 4);
    CP_COMMIT();

    if (tx < 128) {
        int mg = min(bm + tx, NN - 1);
        float cnt = g_cnt[mg];
        sFlag[tx] = (cnt > 0.f) ? 1.f : 0.f;
        sBat[tx] = is64 ? (int)reinterpret_cast<const long long*>(batch)[mg]
                        : reinterpret_cast<const int*>(batch)[mg];
    }

    {
        const int row = tx >> 2;
        int mg = min(bm + row, NN - 1);
        float inv = 1.f / fmaxf(g_cnt[mg], 1.f);
        const float* src = g_aggH + (size_t)mg * HID;
        int kq0 = (tx & 3) * 32;
        stage_A_hi(src + kq0, row, kq0, inv, sAh);
        stage_A_hi(src + kq0 + 128, row, kq0 + 128, inv, sAh);
    }

    const int warp_m = w >> 2, warp_n = w & 3;
    float acc[2][8][4];
#pragma unroll
    for (int mi = 0; mi < 2; ++mi)
#pragma unroll
        for (int ni = 0; ni < 8; ++ni)
#pragma unroll
            for (int q = 0; q < 4; ++q) acc[mi][ni][q] = 0.f;

    // L3 mainloop (16 chunks, single-pass)
#pragma unroll 1
    for (int c = 0; c < 16; ++c) {
        const int buf = c & 1;
        CP_WAIT(0);
        __syncthreads();
        if (c < 15) {
            CP16(sBu + ((buf ^ 1) * 2048 + tx * 4) * 4, g_BfW23 + (c + 1) * 2048 + tx * 4);
            CP_COMMIT();
        }
        mma_chunk1(sAh, sB + buf * 2048, c, warp_m, warp_n, lane, acc);
    }
    __syncthreads();

    // first W4 chunk into buf 0
    if (tx < 256) CP16(sBu + (tx * 4) * 4, g_BfW4 + tx * 4);
    CP_COMMIT();

    // L3 epilogue: hid = relu(acc + pre3 + uW3 + bW*flag), pack (hi only) into A frags
    const int g = lane >> 2, t = lane & 3;
#pragma unroll
    for (int mi = 0; mi < 2; ++mi) {
        const int mt = warp_m * 2 + mi;
        const int rA = warp_m * 32 + mi * 16 + g;
        const int mgA = min(bm + rA, NN - 1);
        const int mgB = min(bm + rA + 8, NN - 1);
        const float flA = sFlag[rA], flB = sFlag[rA + 8];
        const float* p3A = g_pre3 + (size_t)mgA * HID;
        const float* p3B = g_pre3 + (size_t)mgB * HID;
        const float* uwA = g_uW3 + (size_t)sBat[rA] * HID;
        const float* uwB = g_uW3 + (size_t)sBat[rA + 8] * HID;
#pragma unroll
        for (int ni = 0; ni < 8; ++ni) {
            int cb = warp_n * 64 + ni * 8 + t * 2;
            int c = cb >> 4, kk = cb & 15;
            int lane2 = ((g & 7) * 4 + ((kk & 7) >> 1)) ^ (mt << 2);
            int idx = ((c * 8 + mt) * 32 + lane2) * 4 + ((kk >= 8) ? 2 : 0);
            float2 bw = *reinterpret_cast<const float2*>(g_bW + cb);
            {
                float2 p3 = *reinterpret_cast<const float2*>(p3A + cb);
                float2 uw = *reinterpret_cast<const float2*>(uwA + cb);
                float h0 = fmaxf(acc[mi][ni][0] + p3.x + uw.x + bw.x * flA, 0.f);
                float h1 = fmaxf(acc[mi][ni][1] + p3.y + uw.y + bw.y * flA, 0.f);
                sAh[idx] = pkhf(hfr(h0), hfr(h1));
            }
            {
                float2 p3 = *reinterpret_cast<const float2*>(p3B + cb);
                float2 uw = *reinterpret_cast<const float2*>(uwB + cb);
                float h0 = fmaxf(acc[mi][ni][2] + p3.x + uw.x + bw.x * flB, 0.f);
                float h1 = fmaxf(acc[mi][ni][3] + p3.y + uw.y + bw.y * flB, 0.f);
                sAh[idx + 1] = pkhf(hfr(h0), hfr(h1));
            }
        }
    }
    __syncthreads();

    // L4: hid @ W4 (K=256, N=128, single-pass)
    float acc2[2][4][4];
#pragma unroll
    for (int mi = 0; mi < 2; ++mi)
#pragma unroll
        for (int ni = 0; ni < 4; ++ni)
#pragma unroll
            for (int q = 0; q < 4; ++q) acc2[mi][ni][q] = 0.f;

#pragma unroll 1
    for (int c = 0; c < 16; ++c) {
        const int buf = c & 1;
        CP_WAIT(0);
        __syncthreads();
        if (c < 15) {
            if (tx < 256)
                CP16(sBu + ((buf ^ 1) * 2048 + tx * 4) * 4, g_BfW4 + (c + 1) * 1024 + tx * 4);
            CP_COMMIT();
        }
        mma_chunk41(sAh, sB + buf * 2048, c, warp_m, warp_n, lane, acc2);
    }

#pragma unroll
    for (int mi = 0; mi < 2; ++mi) {
        int r0 = bm + warp_m * 32 + mi * 16 + g;
#pragma unroll
        for (int ni = 0; ni < 4; ++ni) {
            int cb = warp_n * 32 + ni * 8 + t * 2;
            float2 bb = *reinterpret_cast<const float2*>(b4 + cb);
            if (r0 < NN)
                *reinterpret_cast<float2*>(out + (size_t)r0 * NOUT + cb) =
                    make_float2(acc2[mi][ni][0] + bb.x, acc2[mi][ni][1] + bb.y);
            if (r0 + 8 < NN)
                *reinterpret_cast<float2*>(out + (size_t)(r0 + 8) * NOUT + cb) =
                    make_float2(acc2[mi][ni][2] + bb.x, acc2[mi][ni][3] + bb.y);
        }
    }
}

// ---------------------------------------------------------------------------
extern "C" void kernel_launch(void* const* d_in, const int* in_sizes, int n_in,
                              void* d_out, int out_size) {
    const float* x  = (const float*)d_in[0];
    const void*  ei = d_in[1];
    const float* ea = (const float*)d_in[2];
    const float* u  = (const float*)d_in[3];
    const void*  bt = d_in[4];
    const float* W1 = (const float*)d_in[5];
    const float* b1 = (const float*)d_in[6];
    const float* W2 = (const float*)d_in[7];
    const float* b2 = (const float*)d_in[8];
    const float* W3 = (const float*)d_in[9];
    const float* b3 = (const float*)d_in[10];
    const float* W4 = (const float*)d_in[11];
    const float* b4 = (const float*)d_in[12];
    float* out = (float*)d_out;

    const int smem_pre  = 32768 * 4;            // 128 KB
    const int smem_edge = 128 * OLD * 4;        // 133.1 KB (mainloop 96 KB fits inside)
    const int smem_node = 20480 * 4;            // 80 KB

    cudaFuncSetAttribute(pre_mma_kernel, cudaFuncAttributeMaxDynamicSharedMemorySize, smem_pre);
    cudaFuncSetAttribute(edge_mma_kernel, cudaFuncAttributeMaxDynamicSharedMemorySize, smem_edge);
    cudaFuncSetAttribute(node_mma_kernel, cudaFuncAttributeMaxDynamicSharedMemorySize, smem_node);

    detect_kernel<<<1, 32>>>((const unsigned int*)ei);
    zero_kernel<<<1024, 256>>>();
    prep_frag_kernel<<<192, 256>>>(W1, W3);
    prep_frag2_kernel<<<192, 256>>>(W2, W3, W4);
    prep_u_kernel<<<NG + 1, 256>>>(u, W3, b3, b2);
    pre_mma_kernel<<<dim3((NN + 127) / 128, 2), 512, smem_pre>>>(x, b1);
    edge_mma_kernel<<<NE / 128, 512, smem_edge>>>(ea, ei);
    node_mma_kernel<<<(NN + 127) / 128, 512, smem_node>>>(bt, b4, out);
}

// round 15
// speedup vs baseline: 1.7110x; 1.1998x over previous
#include <cuda_runtime.h>
#include <cuda_fp16.h>
#include <cstdint>

#define NN 50000
#define NE 640000
#define NF 128
#define EF 128
#define UF 64
#define HID 256
#define NG 64
#define NOUT 128

// ---------------- device global scratch (allocation-free) ----------------
__device__ float g_pre1[(size_t)NN * HID];   // x @ W1[0:128] + b1
__device__ float g_pre3[(size_t)NN * HID];   // x @ W3[0:128]
__device__ float g_aggH[(size_t)NN * HID];   // scatter-sum of h1
__device__ float g_cnt[NN];
__device__ float g_uW3[NG * HID];            // u[g] @ W3[384:448] + b3
__device__ float g_bW[HID];                  // b2 @ W3[128:384]
// fp16 hi-only fragment-layout weight images (m16n8k16)
__device__ uint32_t g_BfE[8 * 2048];         // W1_bot^T  : 8 chunks x 2048 words
__device__ uint32_t g_BfP[8 * 4096];         // [W1top|W3top]^T : 8 chunks x 4096
__device__ uint32_t g_BfW23[16 * 2048];      // W2@W3mid : 16 chunks x 2048
__device__ uint32_t g_BfW4[16 * 1024];       // W4  : 16 chunks x 1024
__device__ int   g_idx64;

// ---------------- helpers ----------------
__device__ __forceinline__ uint32_t smem_u32(const void* p) {
    uint32_t a;
    asm("{ .reg .u64 t; cvta.to.shared.u64 t, %1; cvt.u32.u64 %0, t; }" : "=r"(a) : "l"(p));
    return a;
}
__device__ __forceinline__ uint32_t pkhf(float lo, float hi) {
    uint32_t r;
    asm("cvt.rn.f16x2.f32 %0, %1, %2;" : "=r"(r) : "f"(hi), "f"(lo));
    return r;
}
__device__ __forceinline__ float hfr(float v) {
    return __half2float(__float2half(v));
}
__device__ __forceinline__ void mma16(float d[4], const uint32_t a[4], uint32_t b0, uint32_t b1) {
    asm volatile("mma.sync.aligned.m16n8k16.row.col.f32.f16.f16.f32 "
                 "{%0,%1,%2,%3}, {%4,%5,%6,%7}, {%8,%9}, {%0,%1,%2,%3};"
                 : "+f"(d[0]), "+f"(d[1]), "+f"(d[2]), "+f"(d[3])
                 : "r"(a[0]), "r"(a[1]), "r"(a[2]), "r"(a[3]), "r"(b0), "r"(b1));
}

#define CP16(dst_u32, src_ptr) \
    asm volatile("cp.async.cg.shared.global [%0], [%1], 16;" :: "r"(dst_u32), "l"(src_ptr) : "memory")
#define CP_COMMIT() asm volatile("cp.async.commit_group;" ::: "memory")
#define CP_WAIT(n)  asm volatile("cp.async.wait_group %0;" :: "n"(n) : "memory")

// ---------------- detect int64/int32 indices ----------------
__global__ void detect_kernel(const unsigned int* __restrict__ ei) {
    if (threadIdx.x == 0 && blockIdx.x == 0) {
        int is64 = 1;
        for (int i = 0; i < 32; ++i)
            if (ei[2 * i + 1] != 0u) { is64 = 0; break; }
        g_idx64 = is64;
    }
}

__global__ void zero_kernel() {
    long long tid = (long long)blockIdx.x * blockDim.x + threadIdx.x;
    long long stride = (long long)gridDim.x * blockDim.x;
    float4* a4 = reinterpret_cast<float4*>(g_aggH);
    const long long n4 = (long long)NN * HID / 4;
    for (long long i = tid; i < n4; i += stride) a4[i] = make_float4(0.f, 0.f, 0.f, 0.f);
    for (long long i = tid; i < NN; i += stride) g_cnt[i] = 0.f;
}

// ---------------- prep: fp16 hi fragment images for edge + pre GEMMs ----------------
__global__ void prep_frag_kernel(const float* __restrict__ W1, const float* __restrict__ W3) {
    int gid = blockIdx.x * blockDim.x + threadIdx.x;   // 0..49151
    if (gid < 16384) {
        int kp = gid >> 8, n = gid & 255;
        int k0 = kp * 2;
        float v0 = W1[(size_t)(128 + k0) * HID + n];
        float v1 = W1[(size_t)(128 + k0 + 1) * HID + n];
        int c = k0 >> 4, kk = k0 & 15, nt = n >> 3;
        int reg = (kk >= 8) ? 1 : 0;
        int lane = (n & 7) * 4 + ((kk & 7) >> 1);
        g_BfE[c * 2048 + (nt * 32 + lane) * 2 + reg] = pkhf(hfr(v0), hfr(v1));
    } else if (gid < 49152) {
        int local = gid - 16384;
        int kp = local >> 9, n = local & 511;
        int k0 = kp * 2;
        const float* Wsrc = (n < 256) ? W1 : W3;
        int nc = n & 255;
        float v0 = Wsrc[(size_t)k0 * HID + nc];
        float v1 = Wsrc[(size_t)(k0 + 1) * HID + nc];
        int c = k0 >> 4, kk = k0 & 15, nt = n >> 3;
        int reg = (kk >= 8) ? 1 : 0;
        int lane = (n & 7) * 4 + ((kk & 7) >> 1);
        g_BfP[c * 4096 + (nt * 32 + lane) * 2 + reg] = pkhf(hfr(v0), hfr(v1));
    }
}

// ---------------- prep: node weight frag images (W23 computed inline) ----------------
__global__ void prep_frag2_kernel(const float* __restrict__ W2, const float* __restrict__ W3,
                                  const float* __restrict__ W4) {
    int gid = blockIdx.x * blockDim.x + threadIdx.x;   // 0..49151
    if (gid < 32768) {
        int kp = gid >> 8, n = gid & 255;
        int k0 = kp * 2;
        float acc0 = 0.f, acc1 = 0.f;
        const float* w2a = W2 + (size_t)k0 * HID;
        const float* w2b = w2a + HID;
        for (int j = 0; j < HID; ++j) {
            float w3 = W3[(size_t)(128 + j) * HID + n];
            acc0 += w2a[j] * w3;
            acc1 += w2b[j] * w3;
        }
        int c = k0 >> 4, kk = k0 & 15, nt = n >> 3;
        int reg = (kk >= 8) ? 1 : 0;
        int lane = (n & 7) * 4 + ((kk & 7) >> 1);
        g_BfW23[c * 2048 + (nt * 32 + lane) * 2 + reg] = pkhf(hfr(acc0), hfr(acc1));
    } else if (gid < 49152) {
        int local = gid - 32768;
        int kp = local >> 7, n = local & 127;
        int k0 = kp * 2;
        float v0 = W4[(size_t)k0 * NOUT + n];
        float v1 = W4[(size_t)(k0 + 1) * NOUT + n];
        int c = k0 >> 4, kk = k0 & 15, nt = n >> 3;
        int reg = (kk >= 8) ? 1 : 0;
        int lane = (n & 7) * 4 + ((kk & 7) >> 1);
        g_BfW4[c * 1024 + (nt * 32 + lane) * 2 + reg] = pkhf(hfr(v0), hfr(v1));
    }
}

// ---------------- prep: uW3 ; bW ----------------
__global__ void prep_u_kernel(const float* __restrict__ u, const float* __restrict__ W3,
                              const float* __restrict__ b3, const float* __restrict__ b2) {
    int g = blockIdx.x, n = threadIdx.x;
    if (g < NG) {
        float acc = b3[n];
        for (int j = 0; j < UF; ++j)
            acc += u[g * UF + j] * W3[(size_t)(384 + j) * HID + n];
        g_uW3[g * HID + n] = acc;
    } else {
        float acc = 0.f;
        for (int j = 0; j < HID; ++j)
            acc += b2[j] * W3[(size_t)(128 + j) * HID + n];
        g_bW[n] = acc;
    }
}

// ---------------- shared MMA building blocks (M=128 tiles: 8 mt per chunk) ----------------
// A frag plane: idx = ((c*8+mt)*32 + (laneT ^ (mt<<2)))*4 + reg
//   laneT=(g&7)*4+t, reg=(g>=8)+2*(kk>=8), g=row&15, mt=row>>4, t=(kk&7)>>1
// hi-only, 16-float span (8 threads/row staging)
__device__ __forceinline__ void stage_A_hi16(const float* __restrict__ src, int row, int kq, float scale,
                                             uint32_t* __restrict__ sAh) {
    float4 v[4];
#pragma unroll
    for (int j = 0; j < 4; ++j) v[j] = reinterpret_cast<const float4*>(src)[j];
    const float* vf = reinterpret_cast<const float*>(v);
    const int mt = row >> 4, g = row & 15;
    const int rbase = (g >= 8) ? 1 : 0;
    const int lbase = (g & 7) * 4;
#pragma unroll
    for (int pi = 0; pi < 8; ++pi) {
        float v0 = vf[2 * pi] * scale, v1 = vf[2 * pi + 1] * scale;
        int k = kq + 2 * pi;
        int c = k >> 4, kk = k & 15;
        int reg = rbase + ((kk >= 8) ? 2 : 0);
        int lane2 = (lbase + ((kk & 7) >> 1)) ^ (mt << 2);
        int idx = ((c * 8 + mt) * 32 + lane2) * 4 + reg;
        sAh[idx] = pkhf(hfr(v0), hfr(v1));
    }
}

// hi-only, 32-float span (node staging: 8 threads/row over K=256)
__device__ __forceinline__ void stage_A_hi(const float* __restrict__ src, int row, int kq, float scale,
                                           uint32_t* __restrict__ sAh) {
    float4 v[8];
#pragma unroll
    for (int j = 0; j < 8; ++j) v[j] = reinterpret_cast<const float4*>(src)[j];
    const float* vf = reinterpret_cast<const float*>(v);
    const int mt = row >> 4, g = row & 15;
    const int rbase = (g >= 8) ? 1 : 0;
    const int lbase = (g & 7) * 4;
#pragma unroll
    for (int pi = 0; pi < 16; ++pi) {
        float v0 = vf[2 * pi] * scale, v1 = vf[2 * pi + 1] * scale;
        int k = kq + 2 * pi;
        int c = k >> 4, kk = k & 15;
        int reg = rbase + ((kk >= 8) ? 2 : 0);
        int lane2 = (lbase + ((kk & 7) >> 1)) ^ (mt << 2);
        int idx = ((c * 8 + mt) * 32 + lane2) * 4 + reg;
        sAh[idx] = pkhf(hfr(v0), hfr(v1));
    }
}

// single-pass chunk, warp covers 32 cols of N=256 (ni<4); 32x32 warp tile
__device__ __forceinline__ void mma_chunk8(const uint32_t* __restrict__ sAh,
                                           const uint32_t* __restrict__ sB,
                                           int c, int warp_m, int warp_n, int lane,
                                           float acc[2][4][4]) {
    uint32_t ah[2][4];
#pragma unroll
    for (int ii = 0; ii < 2; ++ii) {
        int mt = warp_m * 2 + ii;
        int base = ((c * 8 + mt) * 32 + (lane ^ (mt << 2))) * 4;
        *reinterpret_cast<uint4*>(ah[ii]) = *reinterpret_cast<const uint4*>(sAh + base);
    }
#pragma unroll
    for (int ni = 0; ni < 4; ++ni) {
        const int nt = warp_n * 4 + ni;
        uint2 bh = *reinterpret_cast<const uint2*>(sB + (nt * 32 + lane) * 2);
        mma16(acc[0][ni], ah[0], bh.x, bh.y);
        mma16(acc[1][ni], ah[1], bh.x, bh.y);
    }
}

// single-pass chunk, warp covers 16 cols of N=128 (ni<2)
__device__ __forceinline__ void mma_chunkL4(const uint32_t* __restrict__ sAh,
                                            const uint32_t* __restrict__ sB,
                                            int c, int warp_m, int warp_n, int lane,
                                            float acc[2][2][4]) {
    uint32_t ah[2][4];
#pragma unroll
    for (int ii = 0; ii < 2; ++ii) {
        int mt = warp_m * 2 + ii;
        int base = ((c * 8 + mt) * 32 + (lane ^ (mt << 2))) * 4;
        *reinterpret_cast<uint4*>(ah[ii]) = *reinterpret_cast<const uint4*>(sAh + base);
    }
#pragma unroll
    for (int ni = 0; ni < 2; ++ni) {
        const int nt = warp_n * 2 + ni;
        uint2 bh = *reinterpret_cast<const uint2*>(sB + (nt * 32 + lane) * 2);
        mma16(acc[0][ni], ah[0], bh.x, bh.y);
        mma16(acc[1][ni], ah[1], bh.x, bh.y);
    }
}

// ---------------- pre kernel (single-pass fp16, 1024 thr): tile 128 x 256 ----------------
__global__ __launch_bounds__(1024, 1) void pre_mma_kernel(const float* __restrict__ x,
                                                          const float* __restrict__ b1) {
    extern __shared__ uint32_t smu[];
    uint32_t* sAh = smu;            // 8192 words (32 KB)
    uint32_t* sB  = smu + 8192;     // 16384 words (64 KB, all 8 chunks)

    const int tx = threadIdx.x;
    const int w = tx >> 5, lane = tx & 31;
    const int bm = blockIdx.x * 128;
    const int y = blockIdx.y;
    const uint32_t sBu = smem_u32(sB);

#pragma unroll
    for (int i = 0; i < 4; ++i) {
        int wi = (i * 1024 + tx) * 4;
        int c = wi >> 11;
        CP16(sBu + wi * 4, g_BfP + c * 4096 + y * 2048 + (wi & 2047));
    }
    CP_COMMIT();

    {
        const int row = tx >> 3, kq = (tx & 7) * 16;
        int mg = min(bm + row, NN - 1);
        stage_A_hi16(x + (size_t)mg * NF + kq, row, kq, 1.f, sAh);
    }

    const int warp_m = w >> 3, warp_n = w & 7;
    float acc[2][4][4];
#pragma unroll
    for (int mi = 0; mi < 2; ++mi)
#pragma unroll
        for (int ni = 0; ni < 4; ++ni)
#pragma unroll
            for (int q = 0; q < 4; ++q) acc[mi][ni][q] = 0.f;

    CP_WAIT(0);
    __syncthreads();

#pragma unroll 1
    for (int c = 0; c < 8; ++c)
        mma_chunk8(sAh, sB + c * 2048, c, warp_m, warp_n, lane, acc);

    const int g = lane >> 2, t = lane & 3;
    float* outp = (y == 0) ? g_pre1 : g_pre3;
#pragma unroll
    for (int mi = 0; mi < 2; ++mi) {
        int r0 = bm + warp_m * 32 + mi * 16 + g;
#pragma unroll
        for (int ni = 0; ni < 4; ++ni) {
            int cb = warp_n * 32 + ni * 8 + t * 2;
            float bb0 = 0.f, bb1 = 0.f;
            if (y == 0) { bb0 = b1[cb]; bb1 = b1[cb + 1]; }
            if (r0 < NN)
                *reinterpret_cast<float2*>(outp + (size_t)r0 * HID + cb) =
                    make_float2(acc[mi][ni][0] + bb0, acc[mi][ni][1] + bb1);
            if (r0 + 8 < NN)
                *reinterpret_cast<float2*>(outp + (size_t)(r0 + 8) * HID + cb) =
                    make_float2(acc[mi][ni][2] + bb0, acc[mi][ni][3] + bb1);
        }
    }
}

// ---------------- edge kernel (single-pass fp16, 1024 thr): 128 edges x 256 ----------------
#define OLD 260
__global__ __launch_bounds__(1024, 1) void edge_mma_kernel(const float* __restrict__ ea,
                                                           const void* __restrict__ eidx) {
    extern __shared__ uint32_t smu[];
    uint32_t* sAh = smu;            // 8192 words (hi only)
    uint32_t* sB  = smu + 8192;     // 16384 words (all 8 chunks)
    __shared__ int sRow[128], sCol[128];

    const int tx = threadIdx.x;
    const int w = tx >> 5, lane = tx & 31;
    const int bm = blockIdx.x * 128;
    const int is64 = g_idx64;
    const uint32_t sBu = smem_u32(sB);

#pragma unroll
    for (int i = 0; i < 4; ++i) {
        int wi = (i * 1024 + tx) * 4;
        CP16(sBu + wi * 4, g_BfE + wi);
    }
    CP_COMMIT();

    if (tx < 128) {
        long long e = bm + tx;
        int rr, cc;
        if (is64) {
            rr = (int)reinterpret_cast<const long long*>(eidx)[e];
            cc = (int)reinterpret_cast<const long long*>(eidx)[NE + e];
        } else {
            rr = reinterpret_cast<const int*>(eidx)[e];
            cc = reinterpret_cast<const int*>(eidx)[NE + e];
        }
        sRow[tx] = rr; sCol[tx] = cc;
        atomicAdd(&g_cnt[cc], 1.0f);
    }

    {
        const int row = tx >> 3, kq = (tx & 7) * 16;
        stage_A_hi16(ea + (size_t)(bm + row) * EF + kq, row, kq, 1.f, sAh);
    }

    const int warp_m = w >> 3, warp_n = w & 7;
    float acc[2][4][4];
#pragma unroll
    for (int mi = 0; mi < 2; ++mi)
#pragma unroll
        for (int ni = 0; ni < 4; ++ni)
#pragma unroll
            for (int q = 0; q < 4; ++q) acc[mi][ni][q] = 0.f;

    CP_WAIT(0);
    __syncthreads();

#pragma unroll 1
    for (int c = 0; c < 8; ++c)
        mma_chunk8(sAh, sB + c * 2048, c, warp_m, warp_n, lane, acc);

    // epilogue: two 64-row passes within the 96 KB footprint
    __syncthreads();
    float* sOut = reinterpret_cast<float*>(smu);   // 64*260 floats = 66.6 KB
    const int g = lane >> 2, t = lane & 3;
#pragma unroll 1
    for (int p = 0; p < 2; ++p) {
        if ((warp_m >> 1) == p) {
#pragma unroll
            for (int mi = 0; mi < 2; ++mi) {
                int r0 = (warp_m * 32 + mi * 16 + g) & 63;
#pragma unroll
                for (int ni = 0; ni < 4; ++ni) {
                    int cb = warp_n * 32 + ni * 8 + t * 2;
                    *reinterpret_cast<float2*>(sOut + r0 * OLD + cb) =
                        make_float2(acc[mi][ni][0], acc[mi][ni][1]);
                    *reinterpret_cast<float2*>(sOut + (r0 + 8) * OLD + cb) =
                        make_float2(acc[mi][ni][2], acc[mi][ni][3]);
                }
            }
        }
        __syncthreads();

#pragma unroll
        for (int rr = 0; rr < 2; ++rr) {
            const int rowl = w * 2 + rr;
            const int grow = p * 64 + rowl;
            const int j0 = lane * 8;
            const float* prow = g_pre1 + (size_t)sRow[grow] * HID + j0;
            float* arow = g_aggH + (size_t)sCol[grow] * HID + j0;
            float4 v0 = *reinterpret_cast<const float4*>(sOut + rowl * OLD + j0);
            float4 v1 = *reinterpret_cast<const float4*>(sOut + rowl * OLD + j0 + 4);
            float4 p0 = *reinterpret_cast<const float4*>(prow);
            float4 p1 = *reinterpret_cast<const float4*>(prow + 4);
            float a0 = fmaxf(v0.x + p0.x, 0.f), a1 = fmaxf(v0.y + p0.y, 0.f);
            float a2 = fmaxf(v0.z + p0.z, 0.f), a3 = fmaxf(v0.w + p0.w, 0.f);
            float a4 = fmaxf(v1.x + p1.x, 0.f), a5 = fmaxf(v1.y + p1.y, 0.f);
            float a6 = fmaxf(v1.z + p1.z, 0.f), a7 = fmaxf(v1.w + p1.w, 0.f);
            asm volatile("red.global.add.v4.f32 [%0], {%1,%2,%3,%4};"
                :: "l"(arow), "f"(a0), "f"(a1), "f"(a2), "f"(a3) : "memory");
            asm volatile("red.global.add.v4.f32 [%0], {%1,%2,%3,%4};"
                :: "l"(arow + 4), "f"(a4), "f"(a5), "f"(a6), "f"(a7) : "memory");
        }
        __syncthreads();
    }
}

// ---------------- node kernel (single-pass fp16, 1024 thr): 128 nodes, K=256 L3 + L4 ----------------
__global__ __launch_bounds__(1024, 1) void node_mma_kernel(const void* __restrict__ batch,
                                                           const float* __restrict__ b4,
                                                           float* __restrict__ out) {
    extern __shared__ uint32_t smu[];
    uint32_t* sAh = smu;            // 16384 words (16 chunks, hi only)
    uint32_t* sB  = smu + 16384;    // 2 x 2048
    __shared__ int sBat[128];
    __shared__ float sFlag[128];

    const int tx = threadIdx.x;
    const int w = tx >> 5, lane = tx & 31;
    const int bm = blockIdx.x * 128;
    const int is64 = g_idx64;
    const uint32_t sBu = smem_u32(sB);

    if (tx < 512) CP16(sBu + (tx * 4) * 4, g_BfW23 + tx * 4);
    CP_COMMIT();

    if (tx < 128) {
        int mg = min(bm + tx, NN - 1);
        float cnt = g_cnt[mg];
        sFlag[tx] = (cnt > 0.f) ? 1.f : 0.f;
        sBat[tx] = is64 ? (int)reinterpret_cast<const long long*>(batch)[mg]
                        : reinterpret_cast<const int*>(batch)[mg];
    }

    {
        const int row = tx >> 3;
        int mg = min(bm + row, NN - 1);
        float inv = 1.f / fmaxf(g_cnt[mg], 1.f);
        const int kq = (tx & 7) * 32;
        stage_A_hi(g_aggH + (size_t)mg * HID + kq, row, kq, inv, sAh);
    }

    const int warp_m = w >> 3, warp_n = w & 7;
    float acc[2][4][4];
#pragma unroll
    for (int mi = 0; mi < 2; ++mi)
#pragma unroll
        for (int ni = 0; ni < 4; ++ni)
#pragma unroll
            for (int q = 0; q < 4; ++q) acc[mi][ni][q] = 0.f;

    // L3 mainloop (16 chunks, single-pass)
#pragma unroll 1
    for (int c = 0; c < 16; ++c) {
        const int buf = c & 1;
        CP_WAIT(0);
        __syncthreads();
        if (c < 15) {
            if (tx < 512)
                CP16(sBu + ((buf ^ 1) * 2048 + tx * 4) * 4, g_BfW23 + (c + 1) * 2048 + tx * 4);
            CP_COMMIT();
        }
        mma_chunk8(sAh, sB + buf * 2048, c, warp_m, warp_n, lane, acc);
    }
    __syncthreads();

    // first W4 chunk into buf 0
    if (tx < 256) CP16(sBu + (tx * 4) * 4, g_BfW4 + tx * 4);
    CP_COMMIT();

    // L3 epilogue: hid = relu(acc + pre3 + uW3 + bW*flag), pack (hi only) into A frags
    const int g = lane >> 2, t = lane & 3;
#pragma unroll
    for (int mi = 0; mi < 2; ++mi) {
        const int mt = warp_m * 2 + mi;
        const int rA = warp_m * 32 + mi * 16 + g;
        const int mgA = min(bm + rA, NN - 1);
        const int mgB = min(bm + rA + 8, NN - 1);
        const float flA = sFlag[rA], flB = sFlag[rA + 8];
        const float* p3A = g_pre3 + (size_t)mgA * HID;
        const float* p3B = g_pre3 + (size_t)mgB * HID;
        const float* uwA = g_uW3 + (size_t)sBat[rA] * HID;
        const float* uwB = g_uW3 + (size_t)sBat[rA + 8] * HID;
#pragma unroll
        for (int ni = 0; ni < 4; ++ni) {
            int cb = warp_n * 32 + ni * 8 + t * 2;
            int c = cb >> 4, kk = cb & 15;
            int lane2 = ((g & 7) * 4 + ((kk & 7) >> 1)) ^ (mt << 2);
            int idx = ((c * 8 + mt) * 32 + lane2) * 4 + ((kk >= 8) ? 2 : 0);
            float2 bw = *reinterpret_cast<const float2*>(g_bW + cb);
            {
                float2 p3 = *reinterpret_cast<const float2*>(p3A + cb);
                float2 uw = *reinterpret_cast<const float2*>(uwA + cb);
                float h0 = fmaxf(acc[mi][ni][0] + p3.x + uw.x + bw.x * flA, 0.f);
                float h1 = fmaxf(acc[mi][ni][1] + p3.y + uw.y + bw.y * flA, 0.f);
                sAh[idx] = pkhf(hfr(h0), hfr(h1));
            }
            {
                float2 p3 = *reinterpret_cast<const float2*>(p3B + cb);
                float2 uw = *reinterpret_cast<const float2*>(uwB + cb);
                float h0 = fmaxf(acc[mi][ni][2] + p3.x + uw.x + bw.x * flB, 0.f);
                float h1 = fmaxf(acc[mi][ni][3] + p3.y + uw.y + bw.y * flB, 0.f);
                sAh[idx + 1] = pkhf(hfr(h0), hfr(h1));
            }
        }
    }
    __syncthreads();

    // L4: hid @ W4 (K=256, N=128, single-pass)
    float acc2[2][2][4];
#pragma unroll
    for (int mi = 0; mi < 2; ++mi)
#pragma unroll
        for (int ni = 0; ni < 2; ++ni)
#pragma unroll
            for (int q = 0; q < 4; ++q) acc2[mi][ni][q] = 0.f;

#pragma unroll 1
    for (int c = 0; c < 16; ++c) {
        const int buf = c & 1;
        CP_WAIT(0);
        __syncthreads();
        if (c < 15) {
            if (tx < 256)
                CP16(sBu + ((buf ^ 1) * 2048 + tx * 4) * 4, g_BfW4 + (c + 1) * 1024 + tx * 4);
            CP_COMMIT();
        }
        mma_chunkL4(sAh, sB + buf * 2048, c, warp_m, warp_n, lane, acc2);
    }

#pragma unroll
    for (int mi = 0; mi < 2; ++mi) {
        int r0 = bm + warp_m * 32 + mi * 16 + g;
#pragma unroll
        for (int ni = 0; ni < 2; ++ni) {
            int cb = warp_n * 16 + ni * 8 + t * 2;
            float2 bb = *reinterpret_cast<const float2*>(b4 + cb);
            if (r0 < NN)
                *reinterpret_cast<float2*>(out + (size_t)r0 * NOUT + cb) =
                    make_float2(acc2[mi][ni][0] + bb.x, acc2[mi][ni][1] + bb.y);
            if (r0 + 8 < NN)
                *reinterpret_cast<float2*>(out + (size_t)(r0 + 8) * NOUT + cb) =
                    make_float2(acc2[mi][ni][2] + bb.x, acc2[mi][ni][3] + bb.y);
        }
    }
}

// ---------------------------------------------------------------------------
extern "C" void kernel_launch(void* const* d_in, const int* in_sizes, int n_in,
                              void* d_out, int out_size) {
    const float* x  = (const float*)d_in[0];
    const void*  ei = d_in[1];
    const float* ea = (const float*)d_in[2];
    const float* u  = (const float*)d_in[3];
    const void*  bt = d_in[4];
    const float* W1 = (const float*)d_in[5];
    const float* b1 = (const float*)d_in[6];
    const float* W2 = (const float*)d_in[7];
    const float* b2 = (const float*)d_in[8];
    const float* W3 = (const float*)d_in[9];
    const float* b3 = (const float*)d_in[10];
    const float* W4 = (const float*)d_in[11];
    const float* b4 = (const float*)d_in[12];
    float* out = (float*)d_out;

    const int smem_pre  = 24576 * 4;            // 96 KB
    const int smem_edge = 24576 * 4;            // 96 KB (sOut 66.6 KB overlays)
    const int smem_node = 20480 * 4;            // 80 KB

    cudaFuncSetAttribute(pre_mma_kernel, cudaFuncAttributeMaxDynamicSharedMemorySize, smem_pre);
    cudaFuncSetAttribute(edge_mma_kernel, cudaFuncAttributeMaxDynamicSharedMemorySize, smem_edge);
    cudaFuncSetAttribute(node_mma_kernel, cudaFuncAttributeMaxDynamicSharedMemorySize, smem_node);

    detect_kernel<<<1, 32>>>((const unsigned int*)ei);
    zero_kernel<<<1024, 256>>>();
    prep_frag_kernel<<<192, 256>>>(W1, W3);
    prep_frag2_kernel<<<192, 256>>>(W2, W3, W4);
    prep_u_kernel<<<NG + 1, 256>>>(u, W3, b3, b2);
    pre_mma_kernel<<<dim3((NN + 127) / 128, 2), 1024, smem_pre>>>(x, b1);
    edge_mma_kernel<<<NE / 128, 1024, smem_edge>>>(ea, ei);
    node_mma_kernel<<<(NN + 127) / 128, 1024, smem_node>>>(bt, b4, out);
}